// round 15
// baseline (speedup 1.0000x reference)
#include <cuda_runtime.h>
#include <cstdint>

// Problem constants (match reference)
#define IMG_H 256
#define IMG_W 256
#define NB    8
#define NP    65536
#define EPSF  1e-5f

#define HW  (IMG_H * IMG_W)
#define BHW (NB * HW)              // 524288
#define BN  (NB * NP)              // 524288

// z encoding: enc(z) = ~bits(z). For positive z, enc is strictly DEcreasing,
// so max(enc) == min(z), and 0 is a natural "empty" value -> zero-init device
// globals cover the first call; scratch is re-zeroed each call for replays.
__device__ unsigned int g_pm[BHW];     // per-pixel max of enc(z); 0 = empty
__device__ unsigned int g_zenc[BHW];   // 5x5 max-filtered enc (fully overwritten)

__device__ __forceinline__ float fast_rcp(float x) {
    float r;
    asm("rcp.approx.f32 %0, %1;" : "=f"(r) : "f"(x));
    return r;
}

// ---------------------------------------------------------------------------
// Pass 1: per-pixel scatter-min, 4 points per thread (3x LDG.128).
// Tail: zero the depth+weight OUTPUT planes (the splat now accumulates
// directly into them; harness poisons d_out, and graph replays must be
// deterministic, so both planes are zeroed at the start of every call).
// ---------------------------------------------------------------------------
__global__ void scatter_pm_kernel(const float4* __restrict__ pts4,
                                  float* __restrict__ out) {
    int idx = blockIdx.x * blockDim.x + threadIdx.x;
    if (idx < BN / 4) {
        float4 a = pts4[3 * idx + 0];
        float4 b = pts4[3 * idx + 1];
        float4 c = pts4[3 * idx + 2];
        unsigned int* pm = g_pm + (idx >> 14) * HW;   // batch = (4*idx)/NP

        float xs[4] = {a.x, a.w, b.z, c.y};
        float ys[4] = {a.y, b.x, b.w, c.z};
        float zs[4] = {a.z, b.y, c.x, c.w};
        #pragma unroll
        for (int k = 0; k < 4; k++) {
            int px = (int)rintf(xs[k]);   // round-half-even == jnp.round
            int py = (int)rintf(ys[k]);
            if (px < 0 || px >= IMG_W || py < 0 || py >= IMG_H) continue;
            atomicMax(&pm[py * IMG_W + px], ~__float_as_uint(zs[k]));
        }
    }

    // Tail: zero depth + weight planes (8 MB total poisoned -> 4 MB zeroed
    // here: out[0 .. 2*BHW) covers both planes).
    float4 zf = make_float4(0.f, 0.f, 0.f, 0.f);
    int stride = gridDim.x * blockDim.x;
    float4* oq = (float4*)out;
    for (int j = idx; j < 2 * BHW / 4; j += stride) {
        oq[j] = zf;
    }
}

// ---------------------------------------------------------------------------
// Pass 2: 5x5 max-filter (== 5x5 min-erosion of z), separable in smem tiles
// ---------------------------------------------------------------------------
#define TILE 32
__global__ void minfilter_kernel() {
    __shared__ unsigned int s[36][36 + 1];
    __shared__ unsigned int h[36][TILE + 1];

    int b  = blockIdx.z;
    int ox = blockIdx.x * TILE;
    int oy = blockIdx.y * TILE;
    const unsigned int* pm = g_pm + b * HW;
    int t = threadIdx.y * blockDim.x + threadIdx.x;  // 256 threads

    for (int i = t; i < 36 * 36; i += 256) {
        int r = i / 36, c = i % 36;
        int gy = oy + r - 2, gx = ox + c - 2;
        unsigned int v = 0;  // OOB -> empty (identity for max)
        if (gy >= 0 && gy < IMG_H && gx >= 0 && gx < IMG_W) v = pm[gy * IMG_W + gx];
        s[r][c] = v;
    }
    __syncthreads();

    for (int i = t; i < 36 * TILE; i += 256) {
        int r = i / TILE, c = i % TILE;
        unsigned int v = s[r][c];
        v = max(v, s[r][c + 1]);
        v = max(v, s[r][c + 2]);
        v = max(v, s[r][c + 3]);
        v = max(v, s[r][c + 4]);
        h[r][c] = v;
    }
    __syncthreads();

    unsigned int* zo = g_zenc + b * HW;
    for (int i = t; i < TILE * TILE; i += 256) {
        int r = i / TILE, c = i % TILE;
        unsigned int v = h[r][c];
        v = max(v, h[r + 1][c]);
        v = max(v, h[r + 2][c]);
        v = max(v, h[r + 3][c]);
        v = max(v, h[r + 4][c]);
        zo[(oy + r) * IMG_W + (ox + c)] = v;
    }
}

// ---------------------------------------------------------------------------
// Pass 3 (FUSED vis + splat, DIRECT TO OUTPUT): each thread computes
// visibility for 4 points and writes vis_out; the warp then iterates the
// ballot of visible points, broadcasting (x,y,z) via shfl, and all 32 lanes
// splat cooperatively: lane = (row 0..7, quarter 0..3), rows 0..6 live, each
// active lane owns a 2-pixel quarter of the even-aligned 8-col window and
// adds its contributions straight into the depth and weight output planes
// (float2 RED.64 per plane when both pixels valid, scalar when one is;
// invalid lanes issue nothing -> no out-of-bounds access, no +0.0f races
// with the vis plane). Weights via rcp.approx (rel err ~1e-7 << 1e-3).
// Tail: re-zeroes g_pm for the next graph replay.
// ---------------------------------------------------------------------------
__global__ void vis_splat_kernel(const float4* __restrict__ pts4,
                                 const float* __restrict__ thr_p,
                                 float* __restrict__ out) {
    // Grid is sized EXACTLY BN/4 threads: all lanes of every warp are live.
    int idx = blockIdx.x * blockDim.x + threadIdx.x;
    float4 a = pts4[3 * idx + 0];
    float4 b = pts4[3 * idx + 1];
    float4 c = pts4[3 * idx + 2];
    float thr = __ldg(thr_p);
    int bb = idx >> 14;                      // warp-uniform
    const unsigned int* ze = g_zenc + bb * HW;

    float xs[4] = {a.x, a.w, b.z, c.y};
    float ys[4] = {a.y, b.x, b.w, c.z};
    float zs[4] = {a.z, b.y, c.x, c.w};
    bool vis[4];
    #pragma unroll
    for (int k = 0; k < 4; k++) {
        int px = (int)rintf(xs[k]);
        int py = (int)rintf(ys[k]);
        bool in_img = (px >= 0) && (px < IMG_W) && (py >= 0) && (py < IMG_H);
        bool v = false;
        if (in_img) {
            float zmin = __uint_as_float(~ze[py * IMG_W + px]);
            v = (zs[k] <= zmin + thr);
        }
        vis[k] = v;
    }
    ((float4*)(out + 2 * BHW))[idx] =
        make_float4(vis[0] ? 1.f : 0.f, vis[1] ? 1.f : 0.f,
                    vis[2] ? 1.f : 0.f, vis[3] ? 1.f : 0.f);

    // --- warp-cooperative splat of this warp's visible points ---
    int lane = threadIdx.x & 31;
    int row  = lane >> 2;                    // 0..7 (row 7 idle)
    int q    = lane & 3;                     // quarter: 2 pixels
    float* outD = out + bb * HW;             // depth plane, this batch
    float* outW = out + BHW + bb * HW;       // weight plane, this batch

    #pragma unroll
    for (int k = 0; k < 4; k++) {
        unsigned int mask = __ballot_sync(0xFFFFFFFFu, vis[k]);
        while (mask) {
            int src = __ffs(mask) - 1;
            mask &= mask - 1u;
            float x = __shfl_sync(0xFFFFFFFFu, xs[k], src);
            float y = __shfl_sync(0xFFFFFFFFu, ys[k], src);
            float z = __shfl_sync(0xFFFFFFFFu, zs[k], src);
            int px = (int)rintf(x);
            int py = (int)rintf(y);
            int ii = py + row - 3;
            if (row < 7 && ii >= 0 && ii < IMG_H) {
                float dy = y - (float)ii;
                float dy2 = dy * dy;
                int jstart = ((px - 3) & ~1) + 2 * q;   // lane's 2-col window
                int j0 = jstart, j1 = jstart + 1;
                float dx0 = x - (float)j0;
                float dx1 = dx0 - 1.0f;
                bool ok0 = (j0 >= px - 3) && (j0 <= px + 3) && (j0 >= 0) && (j0 < IMG_W);
                bool ok1 = (j1 >= px - 3) && (j1 <= px + 3) && (j1 >= 0) && (j1 < IMG_W);
                float w0 = fast_rcp(dx0 * dx0 + dy2 + EPSF);
                float w1 = fast_rcp(dx1 * dx1 + dy2 + EPSF);
                int off = ii * IMG_W + jstart;
                if (ok0 && ok1) {
                    atomicAdd((float2*)(outD + off), make_float2(w0 * z, w1 * z));
                    atomicAdd((float2*)(outW + off), make_float2(w0, w1));
                } else if (ok0) {
                    atomicAdd(outD + off, w0 * z);
                    atomicAdd(outW + off, w0);
                } else if (ok1) {
                    atomicAdd(outD + off + 1, w1 * z);
                    atomicAdd(outW + off + 1, w1);
                }
            }
        }
    }

    // Tail: reset g_pm (already consumed by minfilter this call).
    uint4 zu = make_uint4(0u, 0u, 0u, 0u);
    int stride = gridDim.x * blockDim.x;
    for (int j = idx; j < BHW / 4; j += stride) {
        ((uint4*)g_pm)[j] = zu;
    }
}

// ---------------------------------------------------------------------------
extern "C" void kernel_launch(void* const* d_in, const int* in_sizes, int n_in,
                              void* d_out, int out_size) {
    const float* pts = (const float*)d_in[0];   // [B, N, 3]
    const float* thr = (const float*)d_in[1];   // scalar
    float* out = (float*)d_out;                 // [depth | weight | is_visible]

    const int T = 256;
    scatter_pm_kernel<<<BN / 4 / T, T>>>((const float4*)pts, out);
    dim3 fgrid(IMG_W / TILE, IMG_H / TILE, NB);
    minfilter_kernel<<<fgrid, dim3(32, 8)>>>();
    vis_splat_kernel<<<BN / 4 / T, T>>>((const float4*)pts, thr, out);
}